// round 10
// baseline (speedup 1.0000x reference)
#include <cuda_runtime.h>
#include <cuda_fp16.h>
#include <stdint.h>
#include <math.h>

#define T_SEQ 2048
#define D_EMB 2048
#define HD    128
#define NHEADS 16
#define QK_SCALE 0.08838834764831843f
#define WSCALE 256.0f
#define INV_WSCALE (1.0f / 256.0f)

// ---------------- scratch (no allocs allowed) ----------------
__device__ __half g_Xf[T_SEQ * D_EMB];
__device__ __half g_Rf[T_SEQ * D_EMB];
__device__ __half g_Wq[D_EMB * D_EMB];
__device__ __half g_Wk[D_EMB * D_EMB];
__device__ __half g_Wv[D_EMB * D_EMB];
__device__ __half g_Wo[D_EMB * D_EMB];
__device__ __half g_Qf[T_SEQ * D_EMB];
__device__ __half g_Kf[T_SEQ * D_EMB];
__device__ __half g_Vf[T_SEQ * D_EMB];

// ---------------- PTX helpers (base sm_103-legal only) ----------------
__device__ __forceinline__ uint32_t smem_u32(const void* p) {
    uint32_t a;
    asm("{ .reg .u64 t; cvta.to.shared.u64 t, %1; cvt.u32.u64 %0, t; }"
        : "=r"(a) : "l"(p));
    return a;
}
#define CP_ASYNC16(dst, src) \
    asm volatile("cp.async.cg.shared.global [%0], [%1], 16;" :: "r"(dst), "l"(src))
#define CP_COMMIT() asm volatile("cp.async.commit_group;" ::: "memory")
#define CP_WAIT(n) asm volatile("cp.async.wait_group %0;" :: "n"(n) : "memory")

__device__ __forceinline__ void ldsm_x4(uint32_t& r0, uint32_t& r1, uint32_t& r2,
                                        uint32_t& r3, uint32_t addr) {
    asm volatile("ldmatrix.sync.aligned.m8n8.x4.shared.b16 {%0,%1,%2,%3}, [%4];"
                 : "=r"(r0), "=r"(r1), "=r"(r2), "=r"(r3) : "r"(addr));
}
__device__ __forceinline__ void ldsm_x4_t(uint32_t& r0, uint32_t& r1, uint32_t& r2,
                                          uint32_t& r3, uint32_t addr) {
    asm volatile(
        "ldmatrix.sync.aligned.m8n8.x4.trans.shared.b16 {%0,%1,%2,%3}, [%4];"
        : "=r"(r0), "=r"(r1), "=r"(r2), "=r"(r3) : "r"(addr));
}
__device__ __forceinline__ void mma16816(float* c, const uint32_t* a,
                                         const uint32_t* b) {
    asm volatile(
        "mma.sync.aligned.m16n8k16.row.col.f32.f16.f16.f32 "
        "{%0,%1,%2,%3}, {%4,%5,%6,%7}, {%8,%9}, {%0,%1,%2,%3};"
        : "+f"(c[0]), "+f"(c[1]), "+f"(c[2]), "+f"(c[3])
        : "r"(a[0]), "r"(a[1]), "r"(a[2]), "r"(a[3]), "r"(b[0]), "r"(b[1]));
}
__device__ __forceinline__ uint32_t pack_f16(float x, float y) {
    __half2 h = __floats2half2_rn(x, y);
    return *reinterpret_cast<uint32_t*>(&h);
}

// ---------------- conversion kernels ----------------
__global__ __launch_bounds__(256) void convX(const float* __restrict__ A,
                                             __half* __restrict__ F) {
    const int i = blockIdx.x * 256 + threadIdx.x;
    float4 v = reinterpret_cast<const float4*>(A)[i];
    __half f[4] = {__float2half_rn(v.x), __float2half_rn(v.y),
                   __float2half_rn(v.z), __float2half_rn(v.w)};
    reinterpret_cast<uint2*>(F)[i] = *reinterpret_cast<uint2*>(f);
}

__global__ __launch_bounds__(256) void convW16all(
    const float* __restrict__ Wq, const float* __restrict__ Wk,
    const float* __restrict__ Wv, const float* __restrict__ Wo,
    __half* __restrict__ Hq, __half* __restrict__ Hk,
    __half* __restrict__ Hv, __half* __restrict__ Ho) {
    __shared__ float t[32][33];
    const int z = blockIdx.z;
    const float* W = (z == 0) ? Wq : (z == 1) ? Wk : (z == 2) ? Wv : Wo;
    __half* H = (z == 0) ? Hq : (z == 1) ? Hk : (z == 2) ? Hv : Ho;
    const int hd = (z == 3) ? D_EMB : HD;
    const int n  = (z == 3) ? 0 : (blockIdx.x >> 2);
    const int j0 = (z == 3) ? (blockIdx.x * 32) : ((blockIdx.x & 3) * 32);
    const int k0 = blockIdx.y * 32;
    const int tx = threadIdx.x, ty = threadIdx.y;
    const float* Wn = W + (size_t)n * D_EMB * hd;
#pragma unroll
    for (int y = ty; y < 32; y += 8) t[y][tx] = Wn[(size_t)(k0 + y) * hd + j0 + tx];
    __syncthreads();
#pragma unroll
    for (int y = ty; y < 32; y += 8) {
        H[(size_t)(n * hd + j0 + y) * D_EMB + k0 + tx] =
            __float2half_rn(t[tx][y] * WSCALE);
    }
}

// ---------------- 1-pass fp16 HMMA GEMM (warp 64x64, BK=64) ----------------
#define BM 128
#define BN 128
#define BK 64
#define STAGE_B 32768   // A 16K + B 16K
#define GEMM_SMEM (3 * STAGE_B)

// 128-byte rows, 8 chunks, full-XOR swizzle
__device__ __forceinline__ uint32_t swz8(uint32_t base, int row, int chunk) {
    return base + (((row << 3) + (chunk ^ (row & 7))) << 4);
}

__device__ __forceinline__ void stage_tile64(uint32_t sbase,
                                             const __half* __restrict__ g,
                                             int row0, int k0, int tid) {
#pragma unroll
    for (int u = tid; u < 1024; u += 128) {
        const int row = u >> 3, ch = u & 7;
        const uint32_t dst = swz8(sbase, row, ch);
        const __half* src = g + (size_t)(row0 + row) * D_EMB + k0 + ch * 8;
        CP_ASYNC16(dst, src);
    }
}

__device__ __forceinline__ void stage_all(uint32_t sbase, const __half* Af,
                                          const __half* Bf, int bm, int bn,
                                          int k0, int tid) {
    stage_tile64(sbase + 0,     Af, bm, k0, tid);
    stage_tile64(sbase + 16384, Bf, bn, k0, tid);
    CP_COMMIT();
}

__device__ __forceinline__ void gemm_core1(
    uint32_t sb, const __half* Af, const __half* Bf, int bm, int bn, int tid,
    float acc[4][8][4]) {
    const int lane = tid & 31;
    const int wid = tid >> 5;
    const int wm = wid & 1;
    const int wn = wid >> 1;
    const int lr = lane & 7;
    const int lg = lane >> 3;

#pragma unroll
    for (int mt = 0; mt < 4; mt++)
#pragma unroll
        for (int nt = 0; nt < 8; nt++)
#pragma unroll
            for (int e = 0; e < 4; e++) acc[mt][nt][e] = 0.0f;

    stage_all(sb + 0 * STAGE_B, Af, Bf, bm, bn, 0, tid);
    stage_all(sb + 1 * STAGE_B, Af, Bf, bm, bn, BK, tid);

    const int NITER = D_EMB / BK;  // 32
    for (int c = 0; c < NITER; c++) {
        if (c == NITER - 1) {
            CP_WAIT(0);
        } else {
            CP_WAIT(1);
        }
        __syncthreads();
        if (c + 2 < NITER)
            stage_all(sb + ((c + 2) % 3) * STAGE_B, Af, Bf, bm, bn,
                      (c + 2) * BK, tid);

        const uint32_t sX = sb + (c % 3) * STAGE_B;
        const uint32_t sB = sX + 16384;

#pragma unroll
        for (int kk = 0; kk < 4; kk++) {
            uint32_t a4[4][4];
#pragma unroll
            for (int mt = 0; mt < 4; mt++) {
                const int row = wm * 64 + mt * 16 + lr + (lg & 1) * 8;
                const int ch = kk * 2 + (lg >> 1);
                ldsm_x4(a4[mt][0], a4[mt][1], a4[mt][2], a4[mt][3],
                        swz8(sX, row, ch));
            }
            uint32_t b4[8][2];
#pragma unroll
            for (int np = 0; np < 4; np++) {
                const int row = wn * 64 + np * 16 + lr + (lg >> 1) * 8;
                const int ch = kk * 2 + (lg & 1);
                ldsm_x4(b4[np * 2][0], b4[np * 2][1], b4[np * 2 + 1][0],
                        b4[np * 2 + 1][1], swz8(sB, row, ch));
            }
#pragma unroll
            for (int mt = 0; mt < 4; mt++)
#pragma unroll
                for (int nt = 0; nt < 8; nt++)
                    mma16816(acc[mt][nt], a4[mt], b4[nt]);
        }
    }
    __syncthreads();
}

// fused QKV: z=0 -> Q (scaled); z=1 -> K; z=2 -> V
__global__ __launch_bounds__(128, 2) void gemm_qkv(
    const __half* __restrict__ Xf, const __half* __restrict__ Wq,
    const __half* __restrict__ Wk, const __half* __restrict__ Wv,
    __half* __restrict__ Qf, __half* __restrict__ Kf, __half* __restrict__ Vf) {
    extern __shared__ char sm[];
    const uint32_t sb = smem_u32(sm);
    const int tid = threadIdx.x;
    const int lane = tid & 31;
    const int wid = tid >> 5;
    const int z = blockIdx.z;
    const int bm = blockIdx.y * BM;
    const int bn = blockIdx.x * BN;

    const __half* Bf = (z == 0) ? Wq : (z == 1) ? Wk : Wv;

    float acc[4][8][4];
    gemm_core1(sb, Xf, Bf, bm, bn, tid, acc);

    const int wm = wid & 1;
    const int wn = wid >> 1;
    __half* Dst = (z == 0) ? Qf : (z == 1) ? Kf : Vf;
    const float s = (z == 0) ? (QK_SCALE * INV_WSCALE) : INV_WSCALE;
#pragma unroll
    for (int mt = 0; mt < 4; mt++) {
        const int row = bm + wm * 64 + mt * 16 + (lane >> 2);
#pragma unroll
        for (int nt = 0; nt < 8; nt++) {
            const int col = bn + wn * 64 + nt * 8 + (lane & 3) * 2;
            *reinterpret_cast<uint32_t*>(&Dst[(size_t)row * D_EMB + col]) =
                pack_f16(acc[mt][nt][0] * s, acc[mt][nt][1] * s);
            *reinterpret_cast<uint32_t*>(&Dst[(size_t)(row + 8) * D_EMB + col]) =
                pack_f16(acc[mt][nt][2] * s, acc[mt][nt][3] * s);
        }
    }
}

// out-projection: fp32 output
__global__ __launch_bounds__(128, 2) void gemm_out(
    const __half* __restrict__ Af, const __half* __restrict__ Bf,
    float* __restrict__ C) {
    extern __shared__ char sm[];
    const uint32_t sb = smem_u32(sm);
    const int tid = threadIdx.x;
    const int lane = tid & 31;
    const int wid = tid >> 5;
    const int bm = blockIdx.y * BM;
    const int bn = blockIdx.x * BN;

    float acc[4][8][4];
    gemm_core1(sb, Af, Bf, bm, bn, tid, acc);

    const int wm = wid & 1;
    const int wn = wid >> 1;
#pragma unroll
    for (int mt = 0; mt < 4; mt++) {
        const int row = bm + wm * 64 + mt * 16 + (lane >> 2);
#pragma unroll
        for (int nt = 0; nt < 8; nt++) {
            const int col = bn + wn * 64 + nt * 8 + (lane & 3) * 2;
            *reinterpret_cast<float2*>(&C[(size_t)row * D_EMB + col]) =
                make_float2(acc[mt][nt][0] * INV_WSCALE, acc[mt][nt][1] * INV_WSCALE);
            *reinterpret_cast<float2*>(&C[(size_t)(row + 8) * D_EMB + col]) =
                make_float2(acc[mt][nt][2] * INV_WSCALE, acc[mt][nt][3] * INV_WSCALE);
        }
    }
}

// ---------------- fp16 HMMA flash attention (early P-packing) ----------------
#define ATTN_SMEM 65536

__global__ __launch_bounds__(128, 2) void attn_mma(
    const __half* __restrict__ Qf, const __half* __restrict__ Kf,
    const __half* __restrict__ Vf, __half* __restrict__ Rf) {
    extern __shared__ char sm[];
    const uint32_t sb = smem_u32(sm);
    const uint32_t sQ = sb;
    const uint32_t sK = sb + 32768;
    const uint32_t sV = sb + 49152;

    const int n = blockIdx.y;
    const int m0 = blockIdx.x * 128;
    const int tid = threadIdx.x;
    const int lane = tid & 31;
    const int w = tid >> 5;
    const int lr = lane & 7;
    const int lg = lane >> 3;

    // group 1: Q (128 rows x 256B)
    for (int u = tid; u < 2048; u += 128) {
        const int row = u >> 4, ch = u & 15;
        const uint32_t d = (uint32_t)((row * 16 + (ch ^ (row & 7))) * 16);
        CP_ASYNC16(sQ + d, Qf + (size_t)(m0 + row) * D_EMB + n * HD + ch * 8);
    }
    CP_COMMIT();
    // group 2: K(0)
    for (int u = tid; u < 1024; u += 128) {
        const int row = u >> 4, ch = u & 15;
        const uint32_t d = (uint32_t)((row * 16 + (ch ^ (row & 7))) * 16);
        CP_ASYNC16(sK + d, Kf + (size_t)row * D_EMB + n * HD + ch * 8);
    }
    CP_COMMIT();
    // group 3: V(0)
    for (int u = tid; u < 1024; u += 128) {
        const int row = u >> 4, ch = u & 15;
        const uint32_t d = (uint32_t)((row * 16 + (ch ^ (row & 7))) * 16);
        CP_ASYNC16(sV + d, Vf + (size_t)row * D_EMB + n * HD + ch * 8);
    }
    CP_COMMIT();

    float acc[2][16][4];
#pragma unroll
    for (int mt = 0; mt < 2; mt++)
#pragma unroll
        for (int ht = 0; ht < 16; ht++)
#pragma unroll
            for (int e = 0; e < 4; e++) acc[mt][ht][e] = 0.0f;
    float M0[2] = {-1e30f, -1e30f}, M1[2] = {-1e30f, -1e30f};
    float L0[2] = {0.0f, 0.0f}, L1[2] = {0.0f, 0.0f};

    const int NT = T_SEQ / 64;
    for (int it = 0; it < NT; it++) {
        CP_WAIT(1);
        __syncthreads();

        // ---- S = Q K^T for 2 m-tiles ----
        float c[2][8][4];
#pragma unroll
        for (int mt = 0; mt < 2; mt++)
#pragma unroll
            for (int t = 0; t < 8; t++)
#pragma unroll
                for (int e = 0; e < 4; e++) c[mt][t][e] = 0.0f;

#pragma unroll
        for (int kk = 0; kk < 8; kk++) {
            uint32_t q4[2][4];
#pragma unroll
            for (int mt = 0; mt < 2; mt++) {
                const int row = w * 32 + mt * 16 + lr + (lg & 1) * 8;
                const int ch = kk * 2 + (lg >> 1);
                const uint32_t a = (uint32_t)((row * 16 + (ch ^ (row & 7))) * 16);
                ldsm_x4(q4[mt][0], q4[mt][1], q4[mt][2], q4[mt][3], sQ + a);
            }
#pragma unroll
            for (int np = 0; np < 4; np++) {
                uint32_t k4[4];
                const int row = np * 16 + lr + (lg >> 1) * 8;
                const int ch = kk * 2 + (lg & 1);
                const uint32_t a = (uint32_t)((row * 16 + (ch ^ (row & 7))) * 16);
                ldsm_x4(k4[0], k4[1], k4[2], k4[3], sK + a);
#pragma unroll
                for (int mt = 0; mt < 2; mt++) {
                    mma16816(c[mt][np * 2],     q4[mt], &k4[0]);
                    mma16816(c[mt][np * 2 + 1], q4[mt], &k4[2]);
                }
            }
        }
        __syncthreads();

        // prefetch K(it+1)
        if (it + 1 < NT) {
            for (int u = tid; u < 1024; u += 128) {
                const int row = u >> 4, ch = u & 15;
                const uint32_t d = (uint32_t)((row * 16 + (ch ^ (row & 7))) * 16);
                CP_ASYNC16(sK + d, Kf + (size_t)((it + 1) * 64 + row) * D_EMB +
                                       n * HD + ch * 8);
            }
            CP_COMMIT();
        }

        // ---- online softmax + early fp16 P-packing (frees c registers) ----
        uint32_t P[2][4][4];
#pragma unroll
        for (int mt = 0; mt < 2; mt++) {
            float mx0 = -1e30f, mx1 = -1e30f;
#pragma unroll
            for (int t = 0; t < 8; t++) {
                mx0 = fmaxf(mx0, fmaxf(c[mt][t][0], c[mt][t][1]));
                mx1 = fmaxf(mx1, fmaxf(c[mt][t][2], c[mt][t][3]));
            }
            mx0 = fmaxf(mx0, __shfl_xor_sync(0xffffffffu, mx0, 1));
            mx0 = fmaxf(mx0, __shfl_xor_sync(0xffffffffu, mx0, 2));
            mx1 = fmaxf(mx1, __shfl_xor_sync(0xffffffffu, mx1, 1));
            mx1 = fmaxf(mx1, __shfl_xor_sync(0xffffffffu, mx1, 2));

            const float Mn0 = fmaxf(M0[mt], mx0), Mn1 = fmaxf(M1[mt], mx1);
            const float a0 = __expf(M0[mt] - Mn0), a1 = __expf(M1[mt] - Mn1);
            float sum0 = 0.0f, sum1 = 0.0f;
#pragma unroll
            for (int t = 0; t < 8; t++) {
                c[mt][t][0] = __expf(c[mt][t][0] - Mn0);
                c[mt][t][1] = __expf(c[mt][t][1] - Mn0);
                c[mt][t][2] = __expf(c[mt][t][2] - Mn1);
                c[mt][t][3] = __expf(c[mt][t][3] - Mn1);
                sum0 += c[mt][t][0] + c[mt][t][1];
                sum1 += c[mt][t][2] + c[mt][t][3];
            }
#pragma unroll
            for (int kk = 0; kk < 4; kk++) {
                P[mt][kk][0] = pack_f16(c[mt][kk * 2][0], c[mt][kk * 2][1]);
                P[mt][kk][1] = pack_f16(c[mt][kk * 2][2], c[mt][kk * 2][3]);
                P[mt][kk][2] = pack_f16(c[mt][kk * 2 + 1][0], c[mt][kk * 2 + 1][1]);
                P[mt][kk][3] = pack_f16(c[mt][kk * 2 + 1][2], c[mt][kk * 2 + 1][3]);
            }
            sum0 += __shfl_xor_sync(0xffffffffu, sum0, 1);
            sum0 += __shfl_xor_sync(0xffffffffu, sum0, 2);
            sum1 += __shfl_xor_sync(0xffffffffu, sum1, 1);
            sum1 += __shfl_xor_sync(0xffffffffu, sum1, 2);
            L0[mt] = L0[mt] * a0 + sum0;
            L1[mt] = L1[mt] * a1 + sum1;
            M0[mt] = Mn0;
            M1[mt] = Mn1;
#pragma unroll
            for (int ht = 0; ht < 16; ht++) {
                acc[mt][ht][0] *= a0;
                acc[mt][ht][1] *= a0;
                acc[mt][ht][2] *= a1;
                acc[mt][ht][3] *= a1;
            }
        }

        // V(it) ready
        if (it + 1 < NT) {
            CP_WAIT(1);
        } else {
            CP_WAIT(0);
        }
        __syncthreads();

        // ---- O += P V ----
#pragma unroll
        for (int kk = 0; kk < 4; kk++) {
#pragma unroll
            for (int hq = 0; hq < 8; hq++) {
                uint32_t v4[4];
                const int row = kk * 16 + (lg & 1) * 8 + lr;
                const int ch = hq * 2 + (lg >> 1);
                const uint32_t a = (uint32_t)((row * 16 + (ch ^ (row & 7))) * 16);
                ldsm_x4_t(v4[0], v4[1], v4[2], v4[3], sV + a);
#pragma unroll
                for (int mt = 0; mt < 2; mt++) {
                    mma16816(acc[mt][hq * 2],     P[mt][kk], &v4[0]);
                    mma16816(acc[mt][hq * 2 + 1], P[mt][kk], &v4[2]);
                }
            }
        }
        __syncthreads();

        // prefetch V(it+1)
        if (it + 1 < NT) {
            for (int u = tid; u < 1024; u += 128) {
                const int row = u >> 4, ch = u & 15;
                const uint32_t d = (uint32_t)((row * 16 + (ch ^ (row & 7))) * 16);
                CP_ASYNC16(sV + d, Vf + (size_t)((it + 1) * 64 + row) * D_EMB +
                                       n * HD + ch * 8);
            }
            CP_COMMIT();
        }
    }

#pragma unroll
    for (int mt = 0; mt < 2; mt++) {
        const float i0 = 1.0f / L0[mt], i1 = 1.0f / L1[mt];
        const int rowg = m0 + w * 32 + mt * 16 + (lane >> 2);
#pragma unroll
        for (int ht = 0; ht < 16; ht++) {
            const int col = n * HD + ht * 8 + (lane & 3) * 2;
            *reinterpret_cast<uint32_t*>(&Rf[(size_t)rowg * D_EMB + col]) =
                pack_f16(acc[mt][ht][0] * i0, acc[mt][ht][1] * i0);
            *reinterpret_cast<uint32_t*>(&Rf[(size_t)(rowg + 8) * D_EMB + col]) =
                pack_f16(acc[mt][ht][2] * i1, acc[mt][ht][3] * i1);
        }
    }
}

// ---------------------------------------------------------------------------
extern "C" void kernel_launch(void* const* d_in, const int* in_sizes, int n_in,
                              void* d_out, int out_size) {
    const float* X  = (const float*)d_in[0];
    const float* Wq = (const float*)d_in[1];
    const float* Wk = (const float*)d_in[2];
    const float* Wv = (const float*)d_in[3];
    const float* Wo = (const float*)d_in[4];
    float* out = (float*)d_out;

    __half *xf, *rf, *qf, *kf, *vf, *wq, *wk, *wv, *wo;
    cudaGetSymbolAddress((void**)&xf, g_Xf);
    cudaGetSymbolAddress((void**)&rf, g_Rf);
    cudaGetSymbolAddress((void**)&qf, g_Qf);
    cudaGetSymbolAddress((void**)&kf, g_Kf);
    cudaGetSymbolAddress((void**)&vf, g_Vf);
    cudaGetSymbolAddress((void**)&wq, g_Wq);
    cudaGetSymbolAddress((void**)&wk, g_Wk);
    cudaGetSymbolAddress((void**)&wv, g_Wv);
    cudaGetSymbolAddress((void**)&wo, g_Wo);

    const int NELE4 = T_SEQ * D_EMB / 4 / 256;

    convX<<<NELE4, 256>>>(X, xf);
    convW16all<<<dim3(64, 64, 4), dim3(32, 8)>>>(Wq, Wk, Wv, Wo, wq, wk, wv, wo);

    cudaFuncSetAttribute(gemm_qkv, cudaFuncAttributeMaxDynamicSharedMemorySize,
                         GEMM_SMEM);
    cudaFuncSetAttribute(gemm_out, cudaFuncAttributeMaxDynamicSharedMemorySize,
                         GEMM_SMEM);
    gemm_qkv<<<dim3(D_EMB / BN, T_SEQ / BM, 3), 128, GEMM_SMEM>>>(xf, wq, wk, wv,
                                                                  qf, kf, vf);

    cudaFuncSetAttribute(attn_mma, cudaFuncAttributeMaxDynamicSharedMemorySize,
                         ATTN_SMEM);
    attn_mma<<<dim3(T_SEQ / 128, NHEADS), 128, ATTN_SMEM>>>(qf, kf, vf, rf);

    gemm_out<<<dim3(D_EMB / BN, T_SEQ / BM), 128, GEMM_SMEM>>>(rf, wo, out);
}